// round 6
// baseline (speedup 1.0000x reference)
#include <cuda_runtime.h>
#include <math.h>

// Problem constants
namespace {
constexpr int M   = 16384;   // B*S rows
constexpr int K   = 2048;    // n_embed
constexpr int E   = 64;      // num experts
constexpr int N2  = 128;     // fused output cols (W1 | W2)
constexpr int TK  = 8;       // top-k
constexpr int BM  = 64;
constexpr int BK  = 16;
constexpr int XS_LD = 66;    // padded leading dim for x tile (conflict-free, 8B-aligned)
constexpr int NK  = K / BK;  // 128 k-chunks
}

// Scratch: pre-bias linear outputs [M][128] (cols 0..63 = x@W1, 64..127 = x@W2)
__device__ float g_lin[(size_t)M * N2];

// ---- f32x2 packed math (Blackwell FFMA2) ----
__device__ __forceinline__ unsigned long long dup_f2(float w) {
    unsigned long long r;
    asm("mov.b64 %0, {%1, %1};" : "=l"(r) : "r"(__float_as_uint(w)));
    return r;
}
__device__ __forceinline__ void ffma2(unsigned long long& d, unsigned long long a, unsigned long long b) {
    asm("fma.rn.f32x2 %0, %1, %2, %0;" : "+l"(d) : "l"(a), "l"(b));
}
__device__ __forceinline__ float f2lo(unsigned long long v) { return __uint_as_float((unsigned int)v); }
__device__ __forceinline__ float f2hi(unsigned long long v) { return __uint_as_float((unsigned int)(v >> 32)); }

// ============================================================================
// Kernel A: fused GEMM  g_lin[m, 0:64] = x@W1 ; g_lin[m, 64:128] = x@W2
// BM=64 rows per CTA, all 128 cols, BK=16. 256 threads.
// Per-thread: 4 rows x 8 cols, rows packed in pairs -> 2x8 f32x2 accumulators.
// ============================================================================
__global__ __launch_bounds__(256, 2) void gemm_kernel(
    const float* __restrict__ x, const float* __restrict__ W1, const float* __restrict__ W2)
{
    __shared__ float xs[BK][XS_LD];   // [k][row]
    __shared__ float ws[BK][N2];      // [k][col]

    const int tid  = threadIdx.x;
    const int row0 = blockIdx.x * BM;
    const int ty   = tid >> 4;        // 0..15 -> 4 rows each
    const int tx   = tid & 15;        // 0..15 -> 8 cols each

    // --- global load mapping ---
    // x tile: 64 rows x 16 k = 1024 floats, 1 float4/thread
    const int xrow = tid >> 2;            // 0..63
    const int xk   = (tid & 3) << 2;      // 0,4,8,12
    const float* xptr = x + (size_t)(row0 + xrow) * K + xk;

    // W tile: 16 k x 128 cols = 2048 floats, 2 float4/thread
    const int f0 = tid * 2, f1 = tid * 2 + 1;
    const int k0 = f0 >> 5, cq0 = f0 & 31;     // col quad 0..31 (c = cq*4)
    const int k1 = f1 >> 5, cq1 = f1 & 31;
    const float* wptr0 = (cq0 < 16) ? (W1 + (size_t)k0 * E + cq0 * 4)
                                    : (W2 + (size_t)k0 * E + (cq0 - 16) * 4);
    const float* wptr1 = (cq1 < 16) ? (W1 + (size_t)k1 * E + cq1 * 4)
                                    : (W2 + (size_t)k1 * E + (cq1 - 16) * 4);

    unsigned long long acc[2][8];
    #pragma unroll
    for (int p = 0; p < 2; ++p)
        #pragma unroll
        for (int j = 0; j < 8; ++j) acc[p][j] = 0ull;

    // prefetch chunk 0 into registers
    float4 xf  = *reinterpret_cast<const float4*>(xptr);
    float4 wf0 = *reinterpret_cast<const float4*>(wptr0);
    float4 wf1 = *reinterpret_cast<const float4*>(wptr1);

    for (int kt = 0; kt < NK; ++kt) {
        // stage registers -> smem
        xs[xk + 0][xrow] = xf.x;
        xs[xk + 1][xrow] = xf.y;
        xs[xk + 2][xrow] = xf.z;
        xs[xk + 3][xrow] = xf.w;
        *reinterpret_cast<float4*>(&ws[k0][cq0 * 4]) = wf0;
        *reinterpret_cast<float4*>(&ws[k1][cq1 * 4]) = wf1;
        __syncthreads();

        // prefetch next chunk (overlaps with compute below)
        if (kt + 1 < NK) {
            xf  = *reinterpret_cast<const float4*>(xptr + (size_t)(kt + 1) * BK);
            wf0 = *reinterpret_cast<const float4*>(wptr0 + (size_t)(kt + 1) * BK * E);
            wf1 = *reinterpret_cast<const float4*>(wptr1 + (size_t)(kt + 1) * BK * E);
        }

        #pragma unroll
        for (int k = 0; k < BK; ++k) {
            unsigned long long xv0 = *reinterpret_cast<const unsigned long long*>(&xs[k][ty * 4]);
            unsigned long long xv1 = *reinterpret_cast<const unsigned long long*>(&xs[k][ty * 4 + 2]);
            float wv[8];
            *reinterpret_cast<float4*>(&wv[0]) = *reinterpret_cast<const float4*>(&ws[k][tx * 8]);
            *reinterpret_cast<float4*>(&wv[4]) = *reinterpret_cast<const float4*>(&ws[k][tx * 8 + 4]);
            #pragma unroll
            for (int j = 0; j < 8; ++j) {
                unsigned long long w2 = dup_f2(wv[j]);
                ffma2(acc[0][j], xv0, w2);
                ffma2(acc[1][j], xv1, w2);
            }
        }
        __syncthreads();
    }

    // write 4 rows x 8 cols per thread, vectorized
    #pragma unroll
    for (int p = 0; p < 2; ++p) {
        const int rlo = row0 + ty * 4 + p * 2;
        float4* dlo = reinterpret_cast<float4*>(g_lin + (size_t)rlo * N2 + tx * 8);
        float4* dhi = reinterpret_cast<float4*>(g_lin + (size_t)(rlo + 1) * N2 + tx * 8);
        dlo[0] = make_float4(f2lo(acc[p][0]), f2lo(acc[p][1]), f2lo(acc[p][2]), f2lo(acc[p][3]));
        dlo[1] = make_float4(f2lo(acc[p][4]), f2lo(acc[p][5]), f2lo(acc[p][6]), f2lo(acc[p][7]));
        dhi[0] = make_float4(f2hi(acc[p][0]), f2hi(acc[p][1]), f2hi(acc[p][2]), f2hi(acc[p][3]));
        dhi[1] = make_float4(f2hi(acc[p][4]), f2hi(acc[p][5]), f2hi(acc[p][6]), f2hi(acc[p][7]));
    }
}

// ============================================================================
// Kernel B: per-row epilogue. One warp per row (64 experts -> 2 per lane).
//   mixed = (xW1+b1) + noise * softplus(xW2+b2)
//   full  = softmax(mixed)
//   top-8 (desc, ties -> smaller index), masked softmax over top-8
// Output layout (float32): [sparse_sm (M*64) | topk_idx (M*8) | full (M*64)]
// ============================================================================
__global__ __launch_bounds__(256) void epilogue_kernel(
    const float* __restrict__ noise,
    const float* __restrict__ b1, const float* __restrict__ b2,
    float* __restrict__ out)
{
    const float NEG_INF = __int_as_float(0xff800000);

    const int warp = (blockIdx.x * blockDim.x + threadIdx.x) >> 5;
    const int lane = threadIdx.x & 31;
    if (warp >= M) return;

    const float* lin = g_lin + (size_t)warp * N2;
    float l0 = lin[lane]      + b1[lane];
    float l1 = lin[lane + 32] + b1[lane + 32];
    float s0 = lin[64 + lane] + b2[lane];
    float s1 = lin[96 + lane] + b2[lane + 32];
    float n0 = noise[(size_t)warp * E + lane];
    float n1 = noise[(size_t)warp * E + 32 + lane];

    // numerically stable softplus
    float sp0 = fmaxf(s0, 0.f) + log1pf(expf(-fabsf(s0)));
    float sp1 = fmaxf(s1, 0.f) + log1pf(expf(-fabsf(s1)));

    float m0 = l0 + n0 * sp0;
    float m1 = l1 + n1 * sp1;

    // row max
    float mx = fmaxf(m0, m1);
    #pragma unroll
    for (int o = 16; o > 0; o >>= 1) mx = fmaxf(mx, __shfl_xor_sync(0xffffffffu, mx, o));

    float e0 = expf(m0 - mx), e1 = expf(m1 - mx);
    float sum = e0 + e1;
    #pragma unroll
    for (int o = 16; o > 0; o >>= 1) sum += __shfl_xor_sync(0xffffffffu, sum, o);

    // iterative top-8 (argmax, remove, repeat). Tie -> smaller index = jax.lax.top_k order.
    float w0 = m0, w1 = m1;
    bool sel0 = false, sel1 = false;
    float ssum = 0.f;
    int my_idx = 0;
    #pragma unroll
    for (int kk = 0; kk < TK; ++kk) {
        float cv; int ci;
        if (w0 >= w1) { cv = w0; ci = lane; } else { cv = w1; ci = lane + 32; }
        #pragma unroll
        for (int o = 16; o > 0; o >>= 1) {
            float ov = __shfl_xor_sync(0xffffffffu, cv, o);
            int   oi = __shfl_xor_sync(0xffffffffu, ci, o);
            if (ov > cv || (ov == cv && oi < ci)) { cv = ov; ci = oi; }
        }
        ssum += expf(cv - mx);
        if (ci == lane)      { sel0 = true; w0 = NEG_INF; }
        if (ci == lane + 32) { sel1 = true; w1 = NEG_INF; }
        if (lane == kk) my_idx = ci;
    }

    const float inv_s  = 1.f / sum;
    const float inv_ss = 1.f / ssum;

    float* osp   = out;                              // sparse softmax [M*64]
    float* oidx  = out + (size_t)M * E;              // topk idx as float [M*8]
    float* ofull = oidx + (size_t)M * TK;            // full softmax [M*64]

    osp[(size_t)warp * E + lane]        = sel0 ? e0 * inv_ss : 0.f;
    osp[(size_t)warp * E + 32 + lane]   = sel1 ? e1 * inv_ss : 0.f;
    ofull[(size_t)warp * E + lane]      = e0 * inv_s;
    ofull[(size_t)warp * E + 32 + lane] = e1 * inv_s;
    if (lane < TK) oidx[(size_t)warp * TK + lane] = (float)my_idx;
}

extern "C" void kernel_launch(void* const* d_in, const int* in_sizes, int n_in,
                              void* d_out, int out_size)
{
    (void)in_sizes; (void)n_in; (void)out_size;
    const float* x     = (const float*)d_in[0];
    const float* noise = (const float*)d_in[1];
    const float* W1    = (const float*)d_in[2];
    const float* b1    = (const float*)d_in[3];
    const float* W2    = (const float*)d_in[4];
    const float* b2    = (const float*)d_in[5];
    float* out = (float*)d_out;

    gemm_kernel<<<M / BM, 256>>>(x, W1, W2);
    epilogue_kernel<<<(M * 32 + 255) / 256, 256>>>(noise, b1, b2, out);
}

// round 11
// speedup vs baseline: 2.1100x; 2.1100x over previous
#include <cuda_runtime.h>
#include <cuda_bf16.h>
#include <math.h>
#include <cstdint>

// ============================================================================
// Problem constants
// ============================================================================
namespace {
constexpr int M   = 16384;   // B*S rows
constexpr int K   = 2048;    // n_embed
constexpr int E   = 64;      // num experts
constexpr int N2  = 128;     // fused output cols (W1 | W2)
constexpr int TK  = 8;       // top-k
constexpr int KC  = 32;      // k per pipeline stage
constexpr int NST = K / KC;  // 64 stages
constexpr int RSTR = 80;     // padded B row stride bytes (conflict-free ldmatrix)
constexpr int TILE = 128 * RSTR;       // 10240 B per split tile
constexpr int WSTAGE = 3 * TILE;       // 30720 B per stage (3 splits)
constexpr int NBUF = 4;                // cp.async pipeline depth
constexpr int SMEM_TOTAL = NBUF * WSTAGE;  // 122880 B
constexpr int WCH = WSTAGE / 16;       // 1920 16B chunks per stage
}

// ============================================================================
// Device scratch
// ============================================================================
__device__ float g_lin[(size_t)M * N2];  // cols 0..63 = x@W1, 64..127 = x@W2
// Pre-split W blob: [kc(64)][split(3)][n(128)][RSTR bytes], bf16 k contiguous.
__device__ __align__(16) unsigned char gWB[(size_t)NST * WSTAGE];

// ============================================================================
// Helpers
// ============================================================================
__device__ __forceinline__ uint32_t smem_u32(const void* p) {
    uint32_t a;
    asm("{ .reg .u64 t; cvta.to.shared.u64 t, %1; cvt.u32.u64 %0, t; }" : "=r"(a) : "l"(p));
    return a;
}

#define CP_ASYNC16(dst, src) \
    asm volatile("cp.async.cg.shared.global [%0], [%1], 16;" :: "r"(dst), "l"(src))
#define CP_COMMIT() asm volatile("cp.async.commit_group;" ::: "memory")
#define CP_WAIT2()  asm volatile("cp.async.wait_group 2;" ::: "memory")

#define LDSM_X4(r, addr)                                                        \
    asm volatile("ldmatrix.sync.aligned.m8n8.x4.shared.b16 {%0,%1,%2,%3}, [%4];"\
        : "=r"((r)[0]), "=r"((r)[1]), "=r"((r)[2]), "=r"((r)[3]) : "r"(addr))

__device__ __forceinline__ void mma_acc(float* c, const uint32_t* a, const uint32_t* b) {
    asm volatile(
        "mma.sync.aligned.m16n8k16.row.col.f32.bf16.bf16.f32 "
        "{%0,%1,%2,%3}, {%4,%5,%6,%7}, {%8,%9}, {%0,%1,%2,%3};"
        : "+f"(c[0]), "+f"(c[1]), "+f"(c[2]), "+f"(c[3])
        : "r"(a[0]), "r"(a[1]), "r"(a[2]), "r"(a[3]), "r"(b[0]), "r"(b[1]));
}
__device__ __forceinline__ void mma_zero(float* d, const uint32_t* a, const uint32_t* b) {
    asm volatile(
        "mma.sync.aligned.m16n8k16.row.col.f32.bf16.bf16.f32 "
        "{%0,%1,%2,%3}, {%4,%5,%6,%7}, {%8,%9}, {%10,%11,%12,%13};"
        : "=f"(d[0]), "=f"(d[1]), "=f"(d[2]), "=f"(d[3])
        : "r"(a[0]), "r"(a[1]), "r"(a[2]), "r"(a[3]), "r"(b[0]), "r"(b[1]),
          "f"(0.f), "f"(0.f), "f"(0.f), "f"(0.f));
}

// Bitwise-exact 3-way bf16 split: fp32 24 significand bits = 3 x 8.
// s.a + s.b + s.c == v EXACTLY. bf16 value of each chunk = its high 16 bits.
struct S3 { uint32_t a, b, c; };
__device__ __forceinline__ S3 sp3(float v) {
    S3 s;
    s.a = __float_as_uint(v) & 0xFFFF0000u;
    float r1 = v - __uint_as_float(s.a);          // exact
    s.b = __float_as_uint(r1) & 0xFFFF0000u;
    float r2 = r1 - __uint_as_float(s.b);         // exact, <=8 significand bits
    s.c = __float_as_uint(r2);                    // low 16 mantissa bits are 0
    return s;
}
// Pack two splits' high halves into one bf16x2 fragment register (lo=x, hi=y).
__device__ __forceinline__ uint32_t bp(uint32_t x, uint32_t y) {
    return __byte_perm(x, y, 0x7632);
}

// ============================================================================
// Prep: split W1|W2 (exact masking) into 3 bf16 blobs [kc][split][n][k]
// ============================================================================
__global__ __launch_bounds__(256) void prep_w_kernel(
    const float* __restrict__ W1, const float* __restrict__ W2)
{
    int t   = blockIdx.x * 256 + threadIdx.x;   // 0 .. 262143
    int kin = t & 31;
    int n   = (t >> 5) & 127;
    int kc  = t >> 12;
    int k   = kc * KC + kin;

    float w = (n < E) ? W1[(size_t)k * E + n] : W2[(size_t)k * E + (n - E)];
    S3 s = sp3(w);

    size_t base = (size_t)kc * WSTAGE + (size_t)n * RSTR + kin * 2;
    *reinterpret_cast<unsigned short*>(gWB + base)            = (unsigned short)(s.a >> 16);
    *reinterpret_cast<unsigned short*>(gWB + base + TILE)     = (unsigned short)(s.b >> 16);
    *reinterpret_cast<unsigned short*>(gWB + base + 2 * TILE) = (unsigned short)(s.c >> 16);
}

// ============================================================================
// GEMM: mma.sync bf16x3 with precision-preserving accumulation.
// 128 rows/CTA (8 warps x 16 rows, all 128 cols), 128 CTAs.
// Main product a0*b0: zero-C mma -> RN FFADD into master (no long RZ chains).
// Corrections (a0b1, a1b0, a1b1, a0b2, a2b0): mma-C chains on tiny magnitudes.
// W via 4-deep cp.async pipeline; x LDG'd straight into registers (1-stage
// prefetch) and split in-register via masking + PRMT.
// ============================================================================
__device__ __forceinline__ void issue_stage(uint32_t sb, int tid, int st) {
    const unsigned char* src = gWB + (size_t)st * WSTAGE;
    uint32_t dbase = sb + (uint32_t)(st & (NBUF - 1)) * WSTAGE;
    #pragma unroll
    for (int i = 0; i < 7; ++i) {
        int idx = tid + i * 256;
        CP_ASYNC16(dbase + idx * 16, src + (size_t)idx * 16);
    }
    {
        int idx = tid + 7 * 256;
        if (idx < WCH) CP_ASYNC16(dbase + idx * 16, src + (size_t)idx * 16);
    }
}

__device__ __forceinline__ void load_x(float2* v, const float* xr0, const float* xr1,
                                       int kt, int c2) {
    int kb = kt * KC + c2;
    v[0] = *reinterpret_cast<const float2*>(xr0 + kb);
    v[1] = *reinterpret_cast<const float2*>(xr0 + kb + 8);
    v[2] = *reinterpret_cast<const float2*>(xr0 + kb + 16);
    v[3] = *reinterpret_cast<const float2*>(xr0 + kb + 24);
    v[4] = *reinterpret_cast<const float2*>(xr1 + kb);
    v[5] = *reinterpret_cast<const float2*>(xr1 + kb + 8);
    v[6] = *reinterpret_cast<const float2*>(xr1 + kb + 16);
    v[7] = *reinterpret_cast<const float2*>(xr1 + kb + 24);
}

__global__ __launch_bounds__(256, 1) void gemm_tc_kernel(const float* __restrict__ x)
{
    extern __shared__ unsigned char sm[];
    const uint32_t sb = smem_u32(sm);
    const int tid  = threadIdx.x;
    const int wid  = tid >> 5;
    const int lane = tid & 31;
    const int row0 = blockIdx.x * 128;
    const int m0   = wid * 16;
    const int g    = lane >> 2;          // row-in-group 0..7
    const int c2   = (lane & 3) * 2;     // k-pair base

    const float* xr0 = x + (size_t)(row0 + m0 + g) * K;
    const float* xr1 = xr0 + (size_t)8 * K;

    // B ldmatrix lane addressing
    const int rowB  = (lane & 7) + ((lane & 16) ? 8 : 0);
    const int colB8 = (lane & 8) ? 16 : 0;

    float master[16][4], corr[16][4];
    #pragma unroll
    for (int i = 0; i < 16; ++i)
        #pragma unroll
        for (int j = 0; j < 4; ++j) { master[i][j] = 0.f; corr[i][j] = 0.f; }

    // prologue: 3 stages of W in flight, stage-0 x in regs
    issue_stage(sb, tid, 0); CP_COMMIT();
    issue_stage(sb, tid, 1); CP_COMMIT();
    issue_stage(sb, tid, 2); CP_COMMIT();
    float2 xc[8], xn[8];
    load_x(xc, xr0, xr1, 0, c2);

    for (int kt = 0; kt < NST; ++kt) {
        CP_WAIT2();
        __syncthreads();
        if (kt + 3 < NST) issue_stage(sb, tid, kt + 3);
        CP_COMMIT();
        if (kt + 1 < NST) load_x(xn, xr0, xr1, kt + 1, c2);

        const uint32_t bufb = sb + (uint32_t)(kt & (NBUF - 1)) * WSTAGE;

        #pragma unroll
        for (int sub = 0; sub < 2; ++sub) {
            // ---- A fragments from registers (exact split + PRMT pack) ----
            S3 p00 = sp3(xc[2 * sub].x),     p01 = sp3(xc[2 * sub].y);      // r0 k0,k1
            S3 p08 = sp3(xc[2 * sub + 1].x), p09 = sp3(xc[2 * sub + 1].y);  // r0 k8,k9
            S3 p10 = sp3(xc[4 + 2 * sub].x), p11 = sp3(xc[4 + 2 * sub].y);  // r1 k0,k1
            S3 p18 = sp3(xc[5 + 2 * sub].x), p19 = sp3(xc[5 + 2 * sub].y);  // r1 k8,k9
            uint32_t A0[4] = { bp(p00.a, p01.a), bp(p10.a, p11.a),
                               bp(p08.a, p09.a), bp(p18.a, p19.a) };
            uint32_t A1[4] = { bp(p00.b, p01.b), bp(p10.b, p11.b),
                               bp(p08.b, p09.b), bp(p18.b, p19.b) };
            uint32_t A2[4] = { bp(p00.c, p01.c), bp(p10.c, p11.c),
                               bp(p08.c, p09.c), bp(p18.c, p19.c) };

            const uint32_t k0b = sub * 32;
            #pragma unroll
            for (int np = 0; np < 8; ++np) {
                uint32_t b0[4], b1[4], b2[4];
                uint32_t ab = bufb + (uint32_t)(np * 16 + rowB) * RSTR + k0b + colB8;
                LDSM_X4(b0, ab);
                LDSM_X4(b1, ab + TILE);
                LDSM_X4(b2, ab + 2 * TILE);

                float d[4];
                // ---- block lo (cols np*16 .. np*16+7) ----
                mma_zero(d, A0, &b0[0]);
                #pragma unroll
                for (int j = 0; j < 4; ++j) master[np * 2][j] += d[j];
                mma_acc(corr[np * 2], A0, &b1[0]);
                mma_acc(corr[np * 2], A1, &b0[0]);
                mma_acc(corr[np * 2], A1, &b1[0]);
                mma_acc(corr[np * 2], A0, &b2[0]);
                mma_acc(corr[np * 2], A2, &b0[0]);
                // ---- block hi (cols np*16+8 .. np*16+15) ----
                mma_zero(d, A0, &b0[2]);
                #pragma unroll
                for (int j = 0; j < 4; ++j) master[np * 2 + 1][j] += d[j];
                mma_acc(corr[np * 2 + 1], A0, &b1[2]);
                mma_acc(corr[np * 2 + 1], A1, &b0[2]);
                mma_acc(corr[np * 2 + 1], A1, &b1[2]);
                mma_acc(corr[np * 2 + 1], A0, &b2[2]);
                mma_acc(corr[np * 2 + 1], A2, &b0[2]);
            }
        }

        #pragma unroll
        for (int i = 0; i < 8; ++i) xc[i] = xn[i];
    }

    // ---- write results (master + corr, single RN add) ----
    const int orow = row0 + m0 + g;
    #pragma unroll
    for (int np = 0; np < 16; ++np) {
        float2 vlo = make_float2(master[np][0] + corr[np][0],
                                 master[np][1] + corr[np][1]);
        float2 vhi = make_float2(master[np][2] + corr[np][2],
                                 master[np][3] + corr[np][3]);
        *reinterpret_cast<float2*>(g_lin + (size_t)orow * N2 + np * 8 + c2) = vlo;
        *reinterpret_cast<float2*>(g_lin + (size_t)(orow + 8) * N2 + np * 8 + c2) = vhi;
    }
}

// ============================================================================
// Epilogue: one warp per row (unchanged from R6 pass; 18.8us)
// ============================================================================
__global__ __launch_bounds__(256) void epilogue_kernel(
    const float* __restrict__ noise,
    const float* __restrict__ b1, const float* __restrict__ b2,
    float* __restrict__ out)
{
    const float NEG_INF = __int_as_float(0xff800000);

    const int warp = (blockIdx.x * blockDim.x + threadIdx.x) >> 5;
    const int lane = threadIdx.x & 31;
    if (warp >= M) return;

    const float* lin = g_lin + (size_t)warp * N2;
    float l0 = lin[lane]      + b1[lane];
    float l1 = lin[lane + 32] + b1[lane + 32];
    float s0 = lin[64 + lane] + b2[lane];
    float s1 = lin[96 + lane] + b2[lane + 32];
    float n0 = noise[(size_t)warp * E + lane];
    float n1 = noise[(size_t)warp * E + 32 + lane];

    float sp0 = fmaxf(s0, 0.f) + log1pf(expf(-fabsf(s0)));
    float sp1 = fmaxf(s1, 0.f) + log1pf(expf(-fabsf(s1)));

    float m0 = l0 + n0 * sp0;
    float m1 = l1 + n1 * sp1;

    float mx = fmaxf(m0, m1);
    #pragma unroll
    for (int o = 16; o > 0; o >>= 1) mx = fmaxf(mx, __shfl_xor_sync(0xffffffffu, mx, o));

    float e0 = expf(m0 - mx), e1 = expf(m1 - mx);
    float sum = e0 + e1;
    #pragma unroll
    for (int o = 16; o > 0; o >>= 1) sum += __shfl_xor_sync(0xffffffffu, sum, o);

    float w0 = m0, w1 = m1;
    bool sel0 = false, sel1 = false;
    float ssum = 0.f;
    int my_idx = 0;
    #pragma unroll
    for (int kk = 0; kk < TK; ++kk) {
        float cv; int ci;
        if (w0 >= w1) { cv = w0; ci = lane; } else { cv = w1; ci = lane + 32; }
        #pragma unroll
        for (int o = 16; o > 0; o >>= 1) {
            float ov = __shfl_xor_sync(0xffffffffu, cv, o);
            int   oi = __shfl_xor_sync(0xffffffffu, ci, o);
            if (ov > cv || (ov == cv && oi < ci)) { cv = ov; ci = oi; }
        }
        ssum += expf(cv - mx);
        if (ci == lane)      { sel0 = true; w0 = NEG_INF; }
        if (ci == lane + 32) { sel1 = true; w1 = NEG_INF; }
        if (lane == kk) my_idx = ci;
    }

    const float inv_s  = 1.f / sum;
    const float inv_ss = 1.f / ssum;

    float* osp   = out;
    float* oidx  = out + (size_t)M * E;
    float* ofull = oidx + (size_t)M * TK;

    osp[(size_t)warp * E + lane]        = sel0 ? e0 * inv_ss : 0.f;
    osp[(size_t)warp * E + 32 + lane]   = sel1 ? e1 * inv_ss : 0.f;
    ofull[(size_t)warp * E + lane]      = e0 * inv_s;
    ofull[(size_t)warp * E + 32 + lane] = e1 * inv_s;
    if (lane < TK) oidx[(size_t)warp * TK + lane] = (float)my_idx;
}

// ============================================================================
// Launch
// ============================================================================
extern "C" void kernel_launch(void* const* d_in, const int* in_sizes, int n_in,
                              void* d_out, int out_size)
{
    (void)in_sizes; (void)n_in; (void)out_size;
    const float* x     = (const float*)d_in[0];
    const float* noise = (const float*)d_in[1];
    const float* W1    = (const float*)d_in[2];
    const float* b1    = (const float*)d_in[3];
    const float* W2    = (const float*)d_in[4];
    const float* b2    = (const float*)d_in[5];
    float* out = (float*)d_out;

    static bool attr_done = false;
    if (!attr_done) {
        cudaFuncSetAttribute(gemm_tc_kernel,
                             cudaFuncAttributeMaxDynamicSharedMemorySize, SMEM_TOTAL);
        attr_done = true;
    }

    prep_w_kernel<<<(K * N2) / 256, 256>>>(W1, W2);
    gemm_tc_kernel<<<M / 128, 256, SMEM_TOTAL>>>(x);
    epilogue_kernel<<<(M * 32 + 255) / 256, 256>>>(noise, b1, b2, out);
}

// round 12
// speedup vs baseline: 2.9507x; 1.3984x over previous
#include <cuda_runtime.h>
#include <cuda_fp16.h>
#include <math.h>
#include <cstdint>

// ============================================================================
// Problem constants
// ============================================================================
namespace {
constexpr int M   = 16384;   // B*S rows
constexpr int K   = 2048;    // n_embed
constexpr int E   = 64;      // num experts
constexpr int N2  = 128;     // fused output cols (W1 | W2)
constexpr int TK  = 8;       // top-k
constexpr int KC  = 32;      // k per pipeline stage
constexpr int NST = K / KC;  // 64 stages
constexpr int RSTR = 80;     // padded B row stride bytes (conflict-free ldmatrix)
constexpr int TILE = 128 * RSTR;       // 10240 B per split tile
constexpr int WSTAGE = 2 * TILE;       // 20480 B per stage (2 fp16 splits)
constexpr int NBUF = 4;                // cp.async pipeline depth
constexpr int SMEM_TOTAL = NBUF * WSTAGE;  // 81920 B
constexpr int WCH = WSTAGE / 16;       // 1280 16B chunks per stage (5 per thread)
constexpr float WSCALE   = 1024.0f;    // W pre-scale (avoids fp16 subnormal floor)
constexpr float INV_WSCALE = 1.0f / 1024.0f;
}

// ============================================================================
// Device scratch
// ============================================================================
// pre-bias linear outputs, scaled by WSCALE. cols 0..63 = x@W1, 64..127 = x@W2
__device__ float g_lin[(size_t)M * N2];
// Pre-split W blob: [kc(64)][split(2)][n(128)][RSTR bytes], fp16 k contiguous.
__device__ __align__(16) unsigned char gWB[(size_t)NST * WSTAGE];

// ============================================================================
// Helpers
// ============================================================================
__device__ __forceinline__ uint32_t smem_u32(const void* p) {
    uint32_t a;
    asm("{ .reg .u64 t; cvta.to.shared.u64 t, %1; cvt.u32.u64 %0, t; }" : "=r"(a) : "l"(p));
    return a;
}

#define CP_ASYNC16(dst, src) \
    asm volatile("cp.async.cg.shared.global [%0], [%1], 16;" :: "r"(dst), "l"(src))
#define CP_COMMIT() asm volatile("cp.async.commit_group;" ::: "memory")
#define CP_WAIT2()  asm volatile("cp.async.wait_group 2;" ::: "memory")

#define LDSM_X4(r, addr)                                                        \
    asm volatile("ldmatrix.sync.aligned.m8n8.x4.shared.b16 {%0,%1,%2,%3}, [%4];"\
        : "=r"((r)[0]), "=r"((r)[1]), "=r"((r)[2]), "=r"((r)[3]) : "r"(addr))

__device__ __forceinline__ void mma_acc(float* c, const uint32_t* a, const uint32_t* b) {
    asm volatile(
        "mma.sync.aligned.m16n8k16.row.col.f32.f16.f16.f32 "
        "{%0,%1,%2,%3}, {%4,%5,%6,%7}, {%8,%9}, {%0,%1,%2,%3};"
        : "+f"(c[0]), "+f"(c[1]), "+f"(c[2]), "+f"(c[3])
        : "r"(a[0]), "r"(a[1]), "r"(a[2]), "r"(a[3]), "r"(b[0]), "r"(b[1]));
}
__device__ __forceinline__ void mma_zero(float* d, const uint32_t* a, const uint32_t* b) {
    asm volatile(
        "mma.sync.aligned.m16n8k16.row.col.f32.f16.f16.f32 "
        "{%0,%1,%2,%3}, {%4,%5,%6,%7}, {%8,%9}, {%10,%11,%12,%13};"
        : "=f"(d[0]), "=f"(d[1]), "=f"(d[2]), "=f"(d[3])
        : "r"(a[0]), "r"(a[1]), "r"(a[2]), "r"(a[3]), "r"(b[0]), "r"(b[1]),
          "f"(0.f), "f"(0.f), "f"(0.f), "f"(0.f));
}

// fp16 2-way split of a float2 -> two packed half2 fragment registers.
// v = h0 + h1 + residue (residue <= 2^-24 * |v| + subnormal quantum)
__device__ __forceinline__ void sp2x2(float2 v, uint32_t& a0, uint32_t& a1) {
    __half2 h0 = __floats2half2_rn(v.x, v.y);
    float2 f0 = __half22float2(h0);
    __half2 h1 = __floats2half2_rn(v.x - f0.x, v.y - f0.y);
    a0 = *reinterpret_cast<uint32_t*>(&h0);
    a1 = *reinterpret_cast<uint32_t*>(&h1);
}

// ============================================================================
// Prep: scale W by 2^10, split into 2 fp16 blobs [kc][split][n][k]
// ============================================================================
__global__ __launch_bounds__(256) void prep_w_kernel(
    const float* __restrict__ W1, const float* __restrict__ W2)
{
    int t   = blockIdx.x * 256 + threadIdx.x;   // 0 .. 262143
    int kin = t & 31;
    int n   = (t >> 5) & 127;
    int kc  = t >> 12;
    int k   = kc * KC + kin;

    float w = ((n < E) ? W1[(size_t)k * E + n] : W2[(size_t)k * E + (n - E)]) * WSCALE;
    __half h0 = __float2half_rn(w);
    float r = w - __half2float(h0);
    __half h1 = __float2half_rn(r);

    size_t base = (size_t)kc * WSTAGE + (size_t)n * RSTR + kin * 2;
    *reinterpret_cast<unsigned short*>(gWB + base)        = __half_as_ushort(h0);
    *reinterpret_cast<unsigned short*>(gWB + base + TILE) = __half_as_ushort(h1);
}

// ============================================================================
// GEMM: mma.sync fp16x2-split, 3 products (h0g0 master, h0g1 + h1g0 corr).
// 128 rows/CTA (8 warps x 16 rows, all 128 cols), 128 CTAs.
// Main product: zero-C mma -> RN FFADD into master (no long RZ chains).
// W via 4-deep cp.async pipeline; x LDG'd to regs, split in-register.
// ============================================================================
__device__ __forceinline__ void issue_stage(uint32_t sb, int tid, int st) {
    const unsigned char* src = gWB + (size_t)st * WSTAGE;
    uint32_t dbase = sb + (uint32_t)(st & (NBUF - 1)) * WSTAGE;
    #pragma unroll
    for (int i = 0; i < 5; ++i) {            // 1280 chunks / 256 threads = 5
        int idx = tid + i * 256;
        CP_ASYNC16(dbase + idx * 16, src + (size_t)idx * 16);
    }
}

__device__ __forceinline__ void load_x(float2* v, const float* xr0, const float* xr1,
                                       int kt, int c2) {
    int kb = kt * KC + c2;
    v[0] = *reinterpret_cast<const float2*>(xr0 + kb);
    v[1] = *reinterpret_cast<const float2*>(xr0 + kb + 8);
    v[2] = *reinterpret_cast<const float2*>(xr0 + kb + 16);
    v[3] = *reinterpret_cast<const float2*>(xr0 + kb + 24);
    v[4] = *reinterpret_cast<const float2*>(xr1 + kb);
    v[5] = *reinterpret_cast<const float2*>(xr1 + kb + 8);
    v[6] = *reinterpret_cast<const float2*>(xr1 + kb + 16);
    v[7] = *reinterpret_cast<const float2*>(xr1 + kb + 24);
}

__global__ __launch_bounds__(256, 1) void gemm_tc_kernel(const float* __restrict__ x)
{
    extern __shared__ unsigned char sm[];
    const uint32_t sb = smem_u32(sm);
    const int tid  = threadIdx.x;
    const int wid  = tid >> 5;
    const int lane = tid & 31;
    const int row0 = blockIdx.x * 128;
    const int m0   = wid * 16;
    const int g    = lane >> 2;          // row-in-group 0..7
    const int c2   = (lane & 3) * 2;     // k-pair base

    const float* xr0 = x + (size_t)(row0 + m0 + g) * K;
    const float* xr1 = xr0 + (size_t)8 * K;

    // B ldmatrix lane addressing
    const int rowB  = (lane & 7) + ((lane & 16) ? 8 : 0);
    const int colB8 = (lane & 8) ? 16 : 0;

    float master[16][4], corr[16][4];
    #pragma unroll
    for (int i = 0; i < 16; ++i)
        #pragma unroll
        for (int j = 0; j < 4; ++j) { master[i][j] = 0.f; corr[i][j] = 0.f; }

    // prologue: 3 stages of W in flight, stage-0 x in regs
    issue_stage(sb, tid, 0); CP_COMMIT();
    issue_stage(sb, tid, 1); CP_COMMIT();
    issue_stage(sb, tid, 2); CP_COMMIT();
    float2 xc[8], xn[8];
    load_x(xc, xr0, xr1, 0, c2);

    for (int kt = 0; kt < NST; ++kt) {
        CP_WAIT2();
        __syncthreads();
        if (kt + 3 < NST) issue_stage(sb, tid, kt + 3);
        CP_COMMIT();
        if (kt + 1 < NST) load_x(xn, xr0, xr1, kt + 1, c2);

        const uint32_t bufb = sb + (uint32_t)(kt & (NBUF - 1)) * WSTAGE;

        #pragma unroll
        for (int sub = 0; sub < 2; ++sub) {
            // ---- A fragments from registers (fp16 2-split, packed pairs) ----
            uint32_t A0[4], A1[4];
            sp2x2(xc[2 * sub],     A0[0], A1[0]);   // row g,    k0..k1
            sp2x2(xc[4 + 2 * sub], A0[1], A1[1]);   // row g+8,  k0..k1
            sp2x2(xc[2 * sub + 1], A0[2], A1[2]);   // row g,    k8..k9
            sp2x2(xc[5 + 2 * sub], A0[3], A1[3]);   // row g+8,  k8..k9

            const uint32_t k0b = sub * 32;
            #pragma unroll
            for (int np = 0; np < 8; ++np) {
                uint32_t b0[4], b1[4];
                uint32_t ab = bufb + (uint32_t)(np * 16 + rowB) * RSTR + k0b + colB8;
                LDSM_X4(b0, ab);
                LDSM_X4(b1, ab + TILE);

                float d[4];
                // ---- block lo (cols np*16 .. +7) ----
                mma_zero(d, A0, &b0[0]);
                #pragma unroll
                for (int j = 0; j < 4; ++j) master[np * 2][j] += d[j];
                mma_acc(corr[np * 2], A0, &b1[0]);
                mma_acc(corr[np * 2], A1, &b0[0]);
                // ---- block hi (cols np*16+8 .. +15) ----
                mma_zero(d, A0, &b0[2]);
                #pragma unroll
                for (int j = 0; j < 4; ++j) master[np * 2 + 1][j] += d[j];
                mma_acc(corr[np * 2 + 1], A0, &b1[2]);
                mma_acc(corr[np * 2 + 1], A1, &b0[2]);
            }
        }

        #pragma unroll
        for (int i = 0; i < 8; ++i) xc[i] = xn[i];
    }

    // ---- write results (master + corr, single RN add; still WSCALE-scaled) ----
    const int orow = row0 + m0 + g;
    #pragma unroll
    for (int np = 0; np < 16; ++np) {
        float2 vlo = make_float2(master[np][0] + corr[np][0],
                                 master[np][1] + corr[np][1]);
        float2 vhi = make_float2(master[np][2] + corr[np][2],
                                 master[np][3] + corr[np][3]);
        *reinterpret_cast<float2*>(g_lin + (size_t)orow * N2 + np * 8 + c2) = vlo;
        *reinterpret_cast<float2*>(g_lin + (size_t)(orow + 8) * N2 + np * 8 + c2) = vhi;
    }
}

// ============================================================================
// Epilogue: one warp per row. Applies INV_WSCALE to undo W pre-scaling.
// ============================================================================
__global__ __launch_bounds__(256) void epilogue_kernel(
    const float* __restrict__ noise,
    const float* __restrict__ b1, const float* __restrict__ b2,
    float* __restrict__ out)
{
    const float NEG_INF = __int_as_float(0xff800000);

    const int warp = (blockIdx.x * blockDim.x + threadIdx.x) >> 5;
    const int lane = threadIdx.x & 31;
    if (warp >= M) return;

    const float* lin = g_lin + (size_t)warp * N2;
    float l0 = lin[lane]      * INV_WSCALE + b1[lane];
    float l1 = lin[lane + 32] * INV_WSCALE + b1[lane + 32];
    float s0 = lin[64 + lane] * INV_WSCALE + b2[lane];
    float s1 = lin[96 + lane] * INV_WSCALE + b2[lane + 32];
    float n0 = noise[(size_t)warp * E + lane];
    float n1 = noise[(size_t)warp * E + 32 + lane];

    float sp0 = fmaxf(s0, 0.f) + log1pf(expf(-fabsf(s0)));
    float sp1 = fmaxf(s1, 0.f) + log1pf(expf(-fabsf(s1)));

    float m0 = l0 + n0 * sp0;
    float m1 = l1 + n1 * sp1;

    float mx = fmaxf(m0, m1);
    #pragma unroll
    for (int o = 16; o > 0; o >>= 1) mx = fmaxf(mx, __shfl_xor_sync(0xffffffffu, mx, o));

    float e0 = expf(m0 - mx), e1 = expf(m1 - mx);
    float sum = e0 + e1;
    #pragma unroll
    for (int o = 16; o > 0; o >>= 1) sum += __shfl_xor_sync(0xffffffffu, sum, o);

    float w0 = m0, w1 = m1;
    bool sel0 = false, sel1 = false;
    float ssum = 0.f;
    int my_idx = 0;
    #pragma unroll
    for (int kk = 0; kk < TK; ++kk) {
        float cv; int ci;
        if (w0 >= w1) { cv = w0; ci = lane; } else { cv = w1; ci = lane + 32; }
        #pragma unroll
        for (int o = 16; o > 0; o >>= 1) {
            float ov = __shfl_xor_sync(0xffffffffu, cv, o);
            int   oi = __shfl_xor_sync(0xffffffffu, ci, o);
            if (ov > cv || (ov == cv && oi < ci)) { cv = ov; ci = oi; }
        }
        ssum += expf(cv - mx);
        if (ci == lane)      { sel0 = true; w0 = NEG_INF; }
        if (ci == lane + 32) { sel1 = true; w1 = NEG_INF; }
        if (lane == kk) my_idx = ci;
    }

    const float inv_s  = 1.f / sum;
    const float inv_ss = 1.f / ssum;

    float* osp   = out;
    float* oidx  = out + (size_t)M * E;
    float* ofull = oidx + (size_t)M * TK;

    osp[(size_t)warp * E + lane]        = sel0 ? e0 * inv_ss : 0.f;
    osp[(size_t)warp * E + 32 + lane]   = sel1 ? e1 * inv_ss : 0.f;
    ofull[(size_t)warp * E + lane]      = e0 * inv_s;
    ofull[(size_t)warp * E + 32 + lane] = e1 * inv_s;
    if (lane < TK) oidx[(size_t)warp * TK + lane] = (float)my_idx;
}

// ============================================================================
// Launch
// ============================================================================
extern "C" void kernel_launch(void* const* d_in, const int* in_sizes, int n_in,
                              void* d_out, int out_size)
{
    (void)in_sizes; (void)n_in; (void)out_size;
    const float* x     = (const float*)d_in[0];
    const float* noise = (const float*)d_in[1];
    const float* W1    = (const float*)d_in[2];
    const float* b1    = (const float*)d_in[3];
    const float* W2    = (const float*)d_in[4];
    const float* b2    = (const float*)d_in[5];
    float* out = (float*)d_out;

    static bool attr_done = false;
    if (!attr_done) {
        cudaFuncSetAttribute(gemm_tc_kernel,
                             cudaFuncAttributeMaxDynamicSharedMemorySize, SMEM_TOTAL);
        attr_done = true;
    }

    prep_w_kernel<<<(K * N2) / 256, 256>>>(W1, W2);
    gemm_tc_kernel<<<M / 128, 256, SMEM_TOTAL>>>(x);
    epilogue_kernel<<<(M * 32 + 255) / 256, 256>>>(noise, b1, b2, out);
}